// round 8
// baseline (speedup 1.0000x reference)
#include <cuda_runtime.h>

// ---------------- problem constants ----------------
#define NB 1024
#define NT 128
#define ND 256
#define NH 128
#define NG 512
#define NK 640
#define NSLAB (NK / 32)        // 20
#define NCTA 128

typedef unsigned long long ull;
typedef ulonglong2 ull2;

// ---------------- f32x2 packed math ----------------
__device__ __forceinline__ ull ffma2(ull a, ull b, ull c) {
    ull d;
    asm("fma.rn.f32x2 %0, %1, %2, %3;" : "=l"(d) : "l"(a), "l"(b), "l"(c));
    return d;
}
__device__ __forceinline__ float2 unpack2(ull v) {
    float2 r; asm("mov.b64 {%0, %1}, %2;" : "=f"(r.x), "=f"(r.y) : "l"(v)); return r;
}
__device__ __forceinline__ float sig_fast(float x) { return 1.0f / (1.0f + __expf(-x)); }
__device__ __forceinline__ float tanh_fast(float x) { return 2.0f / (1.0f + __expf(-2.0f * x)) - 1.0f; }

__device__ __forceinline__ unsigned smem_u32(const void* p) {
    unsigned r;
    asm("{ .reg .u64 t; cvta.to.shared.u64 t, %1; cvt.u32.u64 %0, t; }" : "=r"(r) : "l"(p));
    return r;
}
#define CP16(dst, src) asm volatile("cp.async.cg.shared.global [%0], [%1], 16;" :: "r"(dst), "l"(src))
#define CP_COMMIT()    asm volatile("cp.async.commit_group;")
#define CP_WAIT1()     asm volatile("cp.async.wait_group 1;")
#define CP_WAIT0()     asm volatile("cp.async.wait_group 0;")

// ---------------- device scratch ----------------
__device__ float g_pre[(size_t)NT * NB * NG];   // [t*NB+b][rr] gate-reordered
__device__ float g_Wro[NG * NK];                // row rr=4u+gate, cols [W_hh | A_0..A_3]
__device__ float g_Wxro[NG * ND];
__device__ float g_memsm[NH * NH];
__device__ float g_fA[2 * NK];
__device__ float g_h[2][NB * NH];
__device__ float g_hsum[NB * NH];
__device__ float g_biasro[NG];
__device__ float g_c0ro[NG];
__device__ unsigned g_arrive;
__device__ unsigned g_gen;

// ---------------- grid barrier (sense-reversing) ----------------
__device__ __forceinline__ void grid_barrier() {
    __syncthreads();
    if (threadIdx.x == 0) {
        __threadfence();
        unsigned gen = *(volatile unsigned*)&g_gen;
        unsigned t = atomicAdd(&g_arrive, 1u);
        if (t == (unsigned)(gridDim.x - 1)) {
            g_arrive = 0;
            __threadfence();
            *(volatile unsigned*)&g_gen = gen + 1;
        } else {
            while (*(volatile unsigned*)&g_gen == gen) { __nanosleep(64); }
        }
        __threadfence();
    }
    __syncthreads();
}

// ---------------- 8x4 tile (pre_kernel) ----------------
__device__ __forceinline__ void slab84(const char* Ab, const char* Bb,
                                       const int aoff[8], const int boff[4],
                                       ull* acc /*32*/) {
    #pragma unroll
    for (int q = 0; q < 8; q++) {
        ull2 b[4];
        #pragma unroll
        for (int j = 0; j < 4; j++)
            b[j] = *(const ull2*)(Bb + (boff[j] ^ (q << 4)));
        #pragma unroll
        for (int i = 0; i < 8; i++) {
            ull2 a = *(const ull2*)(Ab + (aoff[i] ^ (q << 4)));
            #pragma unroll
            for (int j = 0; j < 4; j++) {
                acc[i * 4 + j] = ffma2(a.x, b[j].x, acc[i * 4 + j]);
                acc[i * 4 + j] = ffma2(a.y, b[j].y, acc[i * 4 + j]);
            }
        }
    }
}

// ---------------- 8x2 tile (recurrence) ----------------
__device__ __forceinline__ void slab82(const char* Ab, const char* Bb,
                                       const int aoff[8], const int boff[2],
                                       ull* acc /*16*/) {
    #pragma unroll
    for (int q = 0; q < 8; q++) {
        ull2 b0v = *(const ull2*)(Bb + (boff[0] ^ (q << 4)));
        ull2 b1v = *(const ull2*)(Bb + (boff[1] ^ (q << 4)));
        #pragma unroll
        for (int i = 0; i < 8; i++) {
            ull2 a = *(const ull2*)(Ab + (aoff[i] ^ (q << 4)));
            acc[i * 2 + 0] = ffma2(a.x, b0v.x, acc[i * 2 + 0]);
            acc[i * 2 + 0] = ffma2(a.y, b0v.y, acc[i * 2 + 0]);
            acc[i * 2 + 1] = ffma2(a.x, b1v.x, acc[i * 2 + 1]);
            acc[i * 2 + 1] = ffma2(a.y, b1v.y, acc[i * 2 + 1]);
        }
    }
}

// ---------------- setup ----------------
__global__ void setup_kernel(const float* __restrict__ memory,
                             const float* __restrict__ b_ih,
                             const float* __restrict__ b_hh,
                             const float* __restrict__ rv0,
                             const float* __restrict__ W_ih) {
    int tid = threadIdx.x;
    float mx = -1e30f;
    for (int m = 0; m < NH; m++) mx = fmaxf(mx, memory[m * NH + tid]);
    float s = 0.f;
    for (int m = 0; m < NH; m++) s += expf(memory[m * NH + tid] - mx);
    float inv = 1.f / s;
    for (int m = 0; m < NH; m++)
        g_memsm[m * NH + tid] = expf(memory[m * NH + tid] - mx) * inv;

    for (int g = tid; g < NG; g += 128) {
        int u = g & 127, gate = g >> 7;
        int rr = 4 * u + gate;
        g_biasro[rr] = b_ih[g] + b_hh[g];
        float c0 = 0.f;
        const float* w = W_ih + (size_t)g * 768 + 256;
        for (int k = 0; k < 512; k++) c0 += rv0[k] * w[k];
        g_c0ro[rr] = c0;
    }
}

// ---------------- fold mem_sm into weights ----------------
__global__ void buildA_kernel(const float* __restrict__ W_ih,
                              const float* __restrict__ W_hh,
                              const float* __restrict__ fc_w) {
    int row = blockIdx.x, q = blockIdx.y, j = threadIdx.x;
    if (row < NG) {
        int u = row >> 2, gate = row & 3;
        int go = gate * 128 + u;
        if (q == 0) {
            g_Wro[(size_t)row * NK + j] = W_hh[(size_t)go * NH + j];
        } else {
            const float* w = W_ih + (size_t)go * 768 + 256 + (q - 1) * 128;
            float s = 0.f;
            for (int m = 0; m < NH; m++) s += w[m] * g_memsm[m * NH + j];
            g_Wro[(size_t)row * NK + q * 128 + j] = s;
        }
    } else {
        int o = row - NG;
        if (q == 0) {
            g_fA[o * NK + j] = fc_w[o * NK + j];
        } else {
            const float* w = fc_w + o * NK + 128 + (q - 1) * 128;
            float s = 0.f;
            for (int m = 0; m < NH; m++) s += w[m] * g_memsm[m * NH + j];
            g_fA[o * NK + q * 128 + j] = s;
        }
    }
}

__global__ void buildX_kernel(const float* __restrict__ W_ih) {
    int row = blockIdx.x, q = blockIdx.y, j = threadIdx.x;
    int u = row >> 2, gate = row & 3;
    int go = gate * 128 + u;
    g_Wxro[(size_t)row * ND + q * 128 + j] = W_ih[(size_t)go * 768 + q * 128 + j];
}

// ---------------- pre: [NT*NB,256] x [256,512] -> g_pre ----------------
__global__ __launch_bounds__(256, 2)
void pre_kernel(const float* __restrict__ x) {
    extern __shared__ char smc[];   // 3 stages x (A 16KB + B 8KB) = 72KB
    int r0  = blockIdx.x * 128;
    int rr0 = blockIdx.y * 64;
    int tid = threadIdx.x;
    int tx = tid & 15, ty = tid >> 4;

    int arow = tid >> 1;
    int aq0 = (tid & 1) * 4;
    int aperm = (arow ^ (arow >> 3)) & 7;
    int bcol = tid >> 2;
    int bq0 = (tid & 3) * 2;
    int bperm = (bcol ^ (bcol >> 3)) & 7;

    int rA = r0 + arow;
    int bb = rA & 1023, tA = rA >> 10;
    const float* xrow = x + ((size_t)bb * NT + tA) * ND;
    const float* wrow = g_Wxro + (size_t)(rr0 + bcol) * ND;
    unsigned smem_base = smem_u32(smc);

    #define PRE_ISSUE(s)                                                        \
    {                                                                           \
        unsigned stg = smem_base + ((s) % 3) * 24576u;                          \
        unsigned ab  = stg + (unsigned)(arow * 128);                            \
        unsigned bbs = stg + 16384u + (unsigned)(bcol * 128);                   \
        const float* ap = xrow + (s) * 32;                                      \
        const float* bp = wrow + (s) * 32;                                      \
        _Pragma("unroll")                                                       \
        for (int p = 0; p < 4; p++) { int qn = aq0 + p; CP16(ab + ((qn ^ aperm) << 4), ap + qn * 4); } \
        _Pragma("unroll")                                                       \
        for (int p = 0; p < 2; p++) { int qn = bq0 + p; CP16(bbs + ((qn ^ bperm) << 4), bp + qn * 4); } \
        CP_COMMIT();                                                            \
    }

    int aoff[8], boff[4];
    #pragma unroll
    for (int i = 0; i < 8; i++)
        aoff[i] = ((ty * 8 + i) * 128) ^ ((((ty ^ i) & 7)) << 4);
    #pragma unroll
    for (int j = 0; j < 4; j++) {
        int cc = tx * 4 + j;
        boff[j] = (cc * 128) ^ ((((cc ^ (cc >> 3)) & 7)) << 4);
    }

    ull acc[32];
    #pragma unroll
    for (int i = 0; i < 32; i++) acc[i] = 0ull;

    const int NS = ND / 32;   // 8
    PRE_ISSUE(0);
    PRE_ISSUE(1);
    for (int s = 0; s < NS; s++) {
        if (s + 2 < NS) { CP_WAIT1(); } else { CP_WAIT0(); }
        __syncthreads();
        if (s + 2 < NS) PRE_ISSUE(s + 2);
        const char* Ab = smc + (s % 3) * 24576;
        slab84(Ab, Ab + 16384, aoff, boff, acc);
    }
    #undef PRE_ISSUE

    int tt = r0 >> 10;
    #pragma unroll
    for (int i = 0; i < 8; i++) {
        int r = r0 + ty * 8 + i;
        int rr = rr0 + tx * 4;
        float2 s0 = unpack2(acc[i * 4 + 0]);
        float2 s1 = unpack2(acc[i * 4 + 1]);
        float2 s2 = unpack2(acc[i * 4 + 2]);
        float2 s3 = unpack2(acc[i * 4 + 3]);
        float4 v;
        v.x = s0.x + s0.y + g_biasro[rr];
        v.y = s1.x + s1.y + g_biasro[rr + 1];
        v.z = s2.x + s2.y + g_biasro[rr + 2];
        v.w = s3.x + s3.y + g_biasro[rr + 3];
        if (tt == 0) {
            v.x += g_c0ro[rr];     v.y += g_c0ro[rr + 1];
            v.z += g_c0ro[rr + 2]; v.w += g_c0ro[rr + 3];
        }
        *(float4*)(g_pre + (size_t)r * NG + rr) = v;
    }
}

// ---------------- persistent recurrence: GEMM + fused LSTM ----------------
// CTA tile: 128 batches x 32 gate-cols (8 units), full K=640.
// smem: Bres 80KB | 3 A-stages x 16KB | Gs 18KB   => 149504 B
__global__ __launch_bounds__(256)
void recur_kernel() {
    extern __shared__ char smc[];
    char* Bres = smc;
    char* Ast  = smc + 81920;
    float* Gs  = (float*)(smc + 131072);   // [128][36] padded

    int tid = threadIdx.x;
    int cta = blockIdx.x;
    int b0  = (cta & 7) << 7;      // 8 batch tiles of 128
    int tu  = cta >> 3;            // 16 unit tiles of 8
    int rr0 = tu << 5;
    int u0  = tu << 3;
    int tx = tid & 15, ty = tid >> 4;

    // zero h0 slice
    {
        int idx = cta * 1024 + tid * 4;
        *(float4*)(g_h[0] + idx) = make_float4(0.f, 0.f, 0.f, 0.f);
    }

    // load resident B: 32 cols x 160 quads (full K)
    {
        unsigned bb = smem_u32(Bres);
        for (int idx = tid; idx < 32 * 160; idx += 256) {
            int c = idx / 160, gq = idx % 160;
            int perm = (c ^ (c >> 3)) & 7;
            int dq = c * 160 + ((gq & ~7) | ((gq & 7) ^ perm));
            CP16(bb + ((unsigned)dq << 4),
                 g_Wro + (size_t)(rr0 + c) * NK + gq * 4);
        }
        CP_COMMIT(); CP_WAIT0();
    }
    grid_barrier();

    // fill-side constants
    int arow = tid >> 1;
    int aq0 = (tid & 1) * 4;
    int aperm = (arow ^ (arow >> 3)) & 7;
    int bA = b0 + arow;
    unsigned asm_base = smem_u32(Ast) + (unsigned)(arow * 128);

    int aoff[8], boff[2];
    #pragma unroll
    for (int i = 0; i < 8; i++)
        aoff[i] = ((ty * 8 + i) * 128) ^ ((((ty ^ i) & 7)) << 4);
    #pragma unroll
    for (int j = 0; j < 2; j++) {
        int cc = tx * 2 + j;
        boff[j] = (cc * 2560) ^ ((((cc ^ (cc >> 3)) & 7)) << 4);
    }

    // LSTM mapping: thread owns 4 cells (b_loc, u0 + ug*4 + 0..3)
    int b_loc = tid & 127;
    int ug = tid >> 7;
    int gb = b0 + b_loc;
    int cidx4 = gb * NH + u0 + ug * 4;
    float4 creg = make_float4(0.f, 0.f, 0.f, 0.f);
    float4 hsreg = make_float4(0.f, 0.f, 0.f, 0.f);

    for (int t = 0; t < NT; t++) {
        const float* __restrict__ Hp = g_h[t & 1];

        #define REC_ISSUE(s)                                                    \
        {                                                                       \
            int k0 = (s) * 32;                                                  \
            int src, col;                                                       \
            if (k0 < 128) { src = bA; col = k0; }                               \
            else { int qd = (k0 - 128) >> 7; src = (4 * bA + qd) & 1023; col = (k0 - 128) & 127; } \
            const float* ap = Hp + src * NH + col;                              \
            unsigned abase = asm_base + ((s) % 3) * 16384u;                     \
            _Pragma("unroll")                                                   \
            for (int p = 0; p < 4; p++) {                                       \
                int qn = aq0 + p;                                               \
                CP16(abase + ((qn ^ aperm) << 4), ap + qn * 4);                 \
            }                                                                   \
            CP_COMMIT();                                                        \
        }

        ull acc[16];
        #pragma unroll
        for (int i = 0; i < 16; i++) acc[i] = 0ull;

        REC_ISSUE(0);
        REC_ISSUE(1);
        for (int s = 0; s < NSLAB; s++) {
            if (s + 2 < NSLAB) { CP_WAIT1(); } else { CP_WAIT0(); }
            __syncthreads();
            if (s + 2 < NSLAB) REC_ISSUE(s + 2);
            slab82(Ast + (s % 3) * 16384, Bres + s * 128, aoff, boff, acc);
        }
        #undef REC_ISSUE

        // write gates to smem (separate buffer — no alias with A stages)
        #pragma unroll
        for (int i = 0; i < 8; i++) {
            float2 g0 = unpack2(acc[i * 2 + 0]);
            float2 g1 = unpack2(acc[i * 2 + 1]);
            float2 gv = make_float2(g0.x + g0.y, g1.x + g1.y);
            *(float2*)(Gs + (ty * 8 + i) * 36 + tx * 2) = gv;
        }

        // prefetch pre for my 4 cells (independent of Gs)
        const float4* PR = (const float4*)(g_pre + ((size_t)t * NB + gb) * NG + rr0 + 16 * ug);
        float4 p0 = PR[0], p1 = PR[1], p2 = PR[2], p3 = PR[3];

        __syncthreads();

        const float* gsr = Gs + b_loc * 36 + 16 * ug;
        float4 G0 = *(const float4*)(gsr + 0);
        float4 G1 = *(const float4*)(gsr + 4);
        float4 G2 = *(const float4*)(gsr + 8);
        float4 G3 = *(const float4*)(gsr + 12);

        float4 hn;
        {
            float gi = G0.x + p0.x, gf = G0.y + p0.y, gg = G0.z + p0.z, go = G0.w + p0.w;
            float cv = sig_fast(gf) * creg.x + sig_fast(gi) * tanh_fast(gg);
            creg.x = cv; hn.x = sig_fast(go) * tanh_fast(cv);
        }
        {
            float gi = G1.x + p1.x, gf = G1.y + p1.y, gg = G1.z + p1.z, go = G1.w + p1.w;
            float cv = sig_fast(gf) * creg.y + sig_fast(gi) * tanh_fast(gg);
            creg.y = cv; hn.y = sig_fast(go) * tanh_fast(cv);
        }
        {
            float gi = G2.x + p2.x, gf = G2.y + p2.y, gg = G2.z + p2.z, go = G2.w + p2.w;
            float cv = sig_fast(gf) * creg.z + sig_fast(gi) * tanh_fast(gg);
            creg.z = cv; hn.z = sig_fast(go) * tanh_fast(cv);
        }
        {
            float gi = G3.x + p3.x, gf = G3.y + p3.y, gg = G3.z + p3.z, go = G3.w + p3.w;
            float cv = sig_fast(gf) * creg.w + sig_fast(gi) * tanh_fast(gg);
            creg.w = cv; hn.w = sig_fast(go) * tanh_fast(cv);
        }

        hsreg.x += hn.x; hsreg.y += hn.y; hsreg.z += hn.z; hsreg.w += hn.w;
        *(float4*)(g_h[(t + 1) & 1] + cidx4) = hn;

        if (t + 1 < NT) grid_barrier();
    }

    *(float4*)(g_hsum + cidx4) = hsreg;
}

// ---------------- final ----------------
__global__ void final_kernel(float* __restrict__ out, const float* __restrict__ fc_b) {
    int b = blockIdx.x * blockDim.x + threadIdx.x;
    if (b >= NB) return;
    #pragma unroll
    for (int o = 0; o < 2; o++) {
        const float* f = g_fA + o * NK;
        const float* hs = g_hsum + b * NH;
        float s = 0.f;
        for (int k = 0; k < NH; k++) s += f[k] * hs[k];
        #pragma unroll
        for (int q = 0; q < 4; q++) {
            const float* hq = g_hsum + ((4 * b + q) & 1023) * NH;
            const float* fq = f + 128 + q * 128;
            for (int m = 0; m < NH; m++) s += fq[m] * hq[m];
        }
        out[b * 2 + o] = fc_b[o] + s * (1.f / (float)NT);
    }
}

// ---------------- launch ----------------
extern "C" void kernel_launch(void* const* d_in, const int* in_sizes, int n_in,
                              void* d_out, int out_size) {
    const float* x      = (const float*)d_in[0];
    const float* memory = (const float*)d_in[1];
    const float* rv0    = (const float*)d_in[2];
    const float* W_ih   = (const float*)d_in[3];
    const float* W_hh   = (const float*)d_in[4];
    const float* b_ih   = (const float*)d_in[5];
    const float* b_hh   = (const float*)d_in[6];
    const float* fc_w   = (const float*)d_in[7];
    const float* fc_b   = (const float*)d_in[8];
    float* out = (float*)d_out;

    static bool attr_done = false;
    if (!attr_done) {
        cudaFuncSetAttribute(pre_kernel, cudaFuncAttributeMaxDynamicSharedMemorySize, 73728);
        cudaFuncSetAttribute(recur_kernel, cudaFuncAttributeMaxDynamicSharedMemorySize, 149504);
        attr_done = true;
    }

    setup_kernel<<<1, 128>>>(memory, b_ih, b_hh, rv0, W_ih);
    buildA_kernel<<<dim3(514, 5), 128>>>(W_ih, W_hh, fc_w);
    buildX_kernel<<<dim3(512, 2), 128>>>(W_ih);
    pre_kernel<<<dim3(NT * NB / 128, NG / 64), 256, 73728>>>(x);
    recur_kernel<<<NCTA, 256, 149504>>>();
    final_kernel<<<4, 256>>>(out, fc_b);
}

// round 10
// speedup vs baseline: 1.3195x; 1.3195x over previous
#include <cuda_runtime.h>
#include <cstdint>

// ---------------- problem constants ----------------
#define NB 1024
#define NT 128
#define ND 256
#define NH 128
#define NG 512
#define NK 640
#define NCTA 128

typedef unsigned long long ull;
typedef ulonglong2 ull2;

// ---------------- f32x2 packed math ----------------
__device__ __forceinline__ ull ffma2(ull a, ull b, ull c) {
    ull d;
    asm("fma.rn.f32x2 %0, %1, %2, %3;" : "=l"(d) : "l"(a), "l"(b), "l"(c));
    return d;
}
__device__ __forceinline__ float2 unpack2(ull v) {
    float2 r; asm("mov.b64 {%0, %1}, %2;" : "=f"(r.x), "=f"(r.y) : "l"(v)); return r;
}
__device__ __forceinline__ float sig_fast(float x) { return 1.0f / (1.0f + __expf(-x)); }
__device__ __forceinline__ float tanh_fast(float x) { return 2.0f / (1.0f + __expf(-2.0f * x)) - 1.0f; }

__device__ __forceinline__ unsigned smem_u32(const void* p) {
    unsigned r;
    asm("{ .reg .u64 t; cvta.to.shared.u64 t, %1; cvt.u32.u64 %0, t; }" : "=r"(r) : "l"(p));
    return r;
}
#define CP16(dst, src) asm volatile("cp.async.cg.shared.global [%0], [%1], 16;" :: "r"(dst), "l"(src))
#define CP_COMMIT()    asm volatile("cp.async.commit_group;")
#define CP_WAIT1()     asm volatile("cp.async.wait_group 1;")
#define CP_WAIT0()     asm volatile("cp.async.wait_group 0;")

// ---------------- device scratch ----------------
__device__ float g_pre[(size_t)NT * NB * NG];   // [t*NB+b][rr] gate-reordered
__device__ float g_Wro[NG * NK];                // row rr=4u+gate, cols [W_hh | A_0..A_3]
__device__ float g_Wxro[NG * ND];
__device__ float g_memsm[NH * NH];
__device__ float g_fA[2 * NK];
__device__ float g_h[2][NB * NH];
__device__ float g_G1[(size_t)NB * NG];         // h @ W_hh^T   [1024][512]
__device__ float g_G2[256 * NG];                // Hg @ Wcat^T  [256][512]
__device__ float g_hsum[NB * NH];
__device__ float g_biasro[NG];
__device__ float g_c0ro[NG];
__device__ unsigned g_arrive;
__device__ unsigned g_gen;

// ---------------- grid barrier (sense-reversing) ----------------
__device__ __forceinline__ void grid_barrier() {
    __syncthreads();
    if (threadIdx.x == 0) {
        __threadfence();
        unsigned gen = *(volatile unsigned*)&g_gen;
        unsigned t = atomicAdd(&g_arrive, 1u);
        if (t == (unsigned)(gridDim.x - 1)) {
            g_arrive = 0;
            __threadfence();
            *(volatile unsigned*)&g_gen = gen + 1;
        } else {
            while (*(volatile unsigned*)&g_gen == gen) { __nanosleep(32); }
        }
        __threadfence();
    }
    __syncthreads();
}

// ---------------- 8x4 f32x2 tile over one 32-k slab ----------------
__device__ __forceinline__ void slab84(const char* Ab, const char* Bb,
                                       const int aoff[8], const int boff[4],
                                       ull* acc /*32*/) {
    #pragma unroll
    for (int q = 0; q < 8; q++) {
        ull2 b[4];
        #pragma unroll
        for (int j = 0; j < 4; j++)
            b[j] = *(const ull2*)(Bb + (boff[j] ^ (q << 4)));
        #pragma unroll
        for (int i = 0; i < 8; i++) {
            ull2 a = *(const ull2*)(Ab + (aoff[i] ^ (q << 4)));
            #pragma unroll
            for (int j = 0; j < 4; j++) {
                acc[i * 4 + j] = ffma2(a.x, b[j].x, acc[i * 4 + j]);
                acc[i * 4 + j] = ffma2(a.y, b[j].y, acc[i * 4 + j]);
            }
        }
    }
}

// ---------------- 2x4 f32x2 tile over one 32-k slab ----------------
__device__ __forceinline__ void slab24(const char* Ab, const char* Bb,
                                       const int aoff[8], const int boff[4],
                                       ull* acc /*8*/) {
    #pragma unroll
    for (int q = 0; q < 8; q++) {
        ull2 b[4];
        #pragma unroll
        for (int j = 0; j < 4; j++)
            b[j] = *(const ull2*)(Bb + (boff[j] ^ (q << 4)));
        #pragma unroll
        for (int i = 0; i < 2; i++) {
            ull2 a = *(const ull2*)(Ab + (aoff[i] ^ (q << 4)));
            #pragma unroll
            for (int j = 0; j < 4; j++) {
                acc[i * 4 + j] = ffma2(a.x, b[j].x, acc[i * 4 + j]);
                acc[i * 4 + j] = ffma2(a.y, b[j].y, acc[i * 4 + j]);
            }
        }
    }
}

// ---------------- setup ----------------
__global__ void setup_kernel(const float* __restrict__ memory,
                             const float* __restrict__ b_ih,
                             const float* __restrict__ b_hh,
                             const float* __restrict__ rv0,
                             const float* __restrict__ W_ih) {
    int tid = threadIdx.x;
    float mx = -1e30f;
    for (int m = 0; m < NH; m++) mx = fmaxf(mx, memory[m * NH + tid]);
    float s = 0.f;
    for (int m = 0; m < NH; m++) s += expf(memory[m * NH + tid] - mx);
    float inv = 1.f / s;
    for (int m = 0; m < NH; m++)
        g_memsm[m * NH + tid] = expf(memory[m * NH + tid] - mx) * inv;

    for (int g = tid; g < NG; g += 128) {
        int u = g & 127, gate = g >> 7;
        int rr = 4 * u + gate;
        g_biasro[rr] = b_ih[g] + b_hh[g];
        float c0 = 0.f;
        const float* w = W_ih + (size_t)g * 768 + 256;
        for (int k = 0; k < 512; k++) c0 += rv0[k] * w[k];
        g_c0ro[rr] = c0;
    }
}

// ---------------- fold mem_sm into weights ----------------
__global__ void buildA_kernel(const float* __restrict__ W_ih,
                              const float* __restrict__ W_hh,
                              const float* __restrict__ fc_w) {
    int row = blockIdx.x, q = blockIdx.y, j = threadIdx.x;
    if (row < NG) {
        int u = row >> 2, gate = row & 3;
        int go = gate * 128 + u;
        if (q == 0) {
            g_Wro[(size_t)row * NK + j] = W_hh[(size_t)go * NH + j];
        } else {
            const float* w = W_ih + (size_t)go * 768 + 256 + (q - 1) * 128;
            float s = 0.f;
            for (int m = 0; m < NH; m++) s += w[m] * g_memsm[m * NH + j];
            g_Wro[(size_t)row * NK + q * 128 + j] = s;
        }
    } else {
        int o = row - NG;
        if (q == 0) {
            g_fA[o * NK + j] = fc_w[o * NK + j];
        } else {
            const float* w = fc_w + o * NK + 128 + (q - 1) * 128;
            float s = 0.f;
            for (int m = 0; m < NH; m++) s += w[m] * g_memsm[m * NH + j];
            g_fA[o * NK + q * 128 + j] = s;
        }
    }
}

__global__ void buildX_kernel(const float* __restrict__ W_ih) {
    int row = blockIdx.x, q = blockIdx.y, j = threadIdx.x;
    int u = row >> 2, gate = row & 3;
    int go = gate * 128 + u;
    g_Wxro[(size_t)row * ND + q * 128 + j] = W_ih[(size_t)go * 768 + q * 128 + j];
}

// ---------------- pre: [NT*NB,256] x [256,512] -> g_pre ----------------
__global__ __launch_bounds__(256, 2)
void pre_kernel(const float* __restrict__ x) {
    extern __shared__ char smc[];
    int r0  = blockIdx.x * 128;
    int rr0 = blockIdx.y * 64;
    int tid = threadIdx.x;
    int tx = tid & 15, ty = tid >> 4;

    int arow = tid >> 1;
    int aq0 = (tid & 1) * 4;
    int aperm = (arow ^ (arow >> 3)) & 7;
    int bcol = tid >> 2;
    int bq0 = (tid & 3) * 2;
    int bperm = (bcol ^ (bcol >> 3)) & 7;

    int rA = r0 + arow;
    int bb = rA & 1023, tA = rA >> 10;
    const float* xrow = x + ((size_t)bb * NT + tA) * ND;
    const float* wrow = g_Wxro + (size_t)(rr0 + bcol) * ND;
    unsigned smem_base = smem_u32(smc);

    #define PRE_ISSUE(s)                                                        \
    {                                                                           \
        unsigned stg = smem_base + ((s) % 3) * 24576u;                          \
        unsigned ab  = stg + (unsigned)(arow * 128);                            \
        unsigned bbs = stg + 16384u + (unsigned)(bcol * 128);                   \
        const float* ap = xrow + (s) * 32;                                      \
        const float* bp = wrow + (s) * 32;                                      \
        _Pragma("unroll")                                                       \
        for (int p = 0; p < 4; p++) { int qn = aq0 + p; CP16(ab + ((qn ^ aperm) << 4), ap + qn * 4); } \
        _Pragma("unroll")                                                       \
        for (int p = 0; p < 2; p++) { int qn = bq0 + p; CP16(bbs + ((qn ^ bperm) << 4), bp + qn * 4); } \
        CP_COMMIT();                                                            \
    }

    int aoff[8], boff[4];
    #pragma unroll
    for (int i = 0; i < 8; i++)
        aoff[i] = ((ty * 8 + i) * 128) ^ ((((ty ^ i) & 7)) << 4);
    #pragma unroll
    for (int j = 0; j < 4; j++) {
        int cc = tx * 4 + j;
        boff[j] = (cc * 128) ^ ((((cc ^ (cc >> 3)) & 7)) << 4);
    }

    ull acc[32];
    #pragma unroll
    for (int i = 0; i < 32; i++) acc[i] = 0ull;

    const int NS = ND / 32;
    PRE_ISSUE(0);
    PRE_ISSUE(1);
    for (int s = 0; s < NS; s++) {
        if (s + 2 < NS) { CP_WAIT1(); } else { CP_WAIT0(); }
        __syncthreads();
        if (s + 2 < NS) PRE_ISSUE(s + 2);
        const char* Ab = smc + (s % 3) * 24576;
        slab84(Ab, Ab + 16384, aoff, boff, acc);
    }
    #undef PRE_ISSUE

    int tt = r0 >> 10;
    #pragma unroll
    for (int i = 0; i < 8; i++) {
        int r = r0 + ty * 8 + i;
        int rr = rr0 + tx * 4;
        float2 s0 = unpack2(acc[i * 4 + 0]);
        float2 s1 = unpack2(acc[i * 4 + 1]);
        float2 s2 = unpack2(acc[i * 4 + 2]);
        float2 s3 = unpack2(acc[i * 4 + 3]);
        float4 v;
        v.x = s0.x + s0.y + g_biasro[rr];
        v.y = s1.x + s1.y + g_biasro[rr + 1];
        v.z = s2.x + s2.y + g_biasro[rr + 2];
        v.w = s3.x + s3.y + g_biasro[rr + 3];
        if (tt == 0) {
            v.x += g_c0ro[rr];     v.y += g_c0ro[rr + 1];
            v.z += g_c0ro[rr + 2]; v.w += g_c0ro[rr + 3];
        }
        *(float4*)(g_pre + (size_t)r * NG + rr) = v;
    }
}

// ---------------- persistent recurrence ----------------
// 128 CTAs. cta<64: G1 job (128 batches x 64 cols, K=128, 4 slabs).
//           cta>=64: G2 job (32 Hg-rows x 64 cols, K=512, 16 slabs).
// B resident for all steps; A (64KB) loaded once per step; zero mid-compute syncs.
// smem layout (1KB-aligned): B @0 (up to 128KB) | A @131072 (64KB)
__global__ __launch_bounds__(256)
void recur_kernel() {
    extern __shared__ char dsm[];
    unsigned raw = smem_u32(dsm);
    unsigned db = (raw + 1023u) & ~1023u;
    char* smb = dsm + (db - raw);
    unsigned Bsm = db;
    unsigned Asm = db + 131072u;
    char* Bp = smb;
    char* Ap = smb + 131072;

    int tid = threadIdx.x;
    int cta = blockIdx.x;
    bool isG1 = cta < 64;
    int jt = isG1 ? cta : cta - 64;
    int rr0 = (jt >> 3) * 64;
    int b0 = (jt & 7) * 128;       // G1 batch tile
    int r0 = (jt & 7) * 32;        // G2 Hg-row tile
    int tx = tid & 15, ty = tid >> 4;

    // LSTM cell ownership: 4 units of one batch
    int T = cta * 256 + tid;
    int b_l = T >> 5;
    int uq = T & 31;

    // zero my h[0] cells
    *(float4*)(&g_h[0][b_l * NH + 4 * uq]) = make_float4(0.f, 0.f, 0.f, 0.f);

    // resident B fill
    {
        int nsl = isG1 ? 4 : 16;
        int koff = isG1 ? 0 : 128;
        for (int ci = tid; ci < nsl * 512; ci += 256) {
            int s = ci >> 9;
            int rem = ci & 511;
            int c = rem >> 3, qn = rem & 7;
            int perm = (c ^ (c >> 3)) & 7;
            CP16(Bsm + (unsigned)(s * 8192 + c * 128 + ((qn ^ perm) << 4)),
                 g_Wro + (size_t)(rr0 + c) * NK + koff + s * 32 + qn * 4);
        }
        CP_COMMIT(); CP_WAIT0();
    }
    grid_barrier();

    int aoff[8], boff[4];
    if (isG1) {
        #pragma unroll
        for (int i = 0; i < 8; i++) {
            int row = ty * 8 + i;
            aoff[i] = (row * 128) ^ ((((row ^ (row >> 3)) & 7)) << 4);
        }
    } else {
        #pragma unroll
        for (int i = 0; i < 2; i++) {
            int row = ty * 2 + i;
            aoff[i] = (row * 128) ^ ((((row ^ (row >> 3)) & 7)) << 4);
        }
    }
    #pragma unroll
    for (int j = 0; j < 4; j++) {
        int cc = tx * 4 + j;
        boff[j] = (cc * 128) ^ ((((cc ^ (cc >> 3)) & 7)) << 4);
    }

    float creg[4] = {0.f, 0.f, 0.f, 0.f};
    float hsum4[4] = {0.f, 0.f, 0.f, 0.f};

    for (int t = 0; t < NT; t++) {
        const float* hb = g_h[t & 1];

        // A fill: 64KB in one burst (16 CP16/thread)
        if (isG1) {
            #pragma unroll
            for (int i = 0; i < 16; i++) {
                int ci = i * 256 + tid;
                int s = ci >> 10, rem = ci & 1023, r = rem >> 3, qn = rem & 7;
                int perm = (r ^ (r >> 3)) & 7;
                CP16(Asm + (unsigned)(s * 16384 + r * 128 + ((qn ^ perm) << 4)),
                     hb + (size_t)(b0 + r) * NH + s * 32 + qn * 4);
            }
        } else {
            #pragma unroll
            for (int i = 0; i < 16; i++) {
                int ci = i * 256 + tid;
                int s = ci >> 8, rem = ci & 255, r = rem >> 3, qn = rem & 7;
                int perm = (r ^ (r >> 3)) & 7;
                CP16(Asm + (unsigned)(s * 4096 + r * 128 + ((qn ^ perm) << 4)),
                     hb + (size_t)r0 * 512 + r * 512 + s * 32 + qn * 4);
            }
        }
        CP_COMMIT();

        // prefetch pre for my LSTM cells (independent of cp.async)
        float pr[16];
        {
            const float4* PR = (const float4*)(g_pre + ((size_t)t * NB + b_l) * NG + 16 * uq);
            #pragma unroll
            for (int w = 0; w < 4; w++) *(float4*)(pr + 4 * w) = PR[w];
        }

        CP_WAIT0();
        __syncthreads();

        if (isG1) {
            ull acc[32];
            #pragma unroll
            for (int i = 0; i < 32; i++) acc[i] = 0ull;
            #pragma unroll
            for (int s = 0; s < 4; s++)
                slab84(Ap + s * 16384, Bp + s * 8192, aoff, boff, acc);
            #pragma unroll
            for (int i = 0; i < 8; i++) {
                float2 s0 = unpack2(acc[i * 4 + 0]);
                float2 s1 = unpack2(acc[i * 4 + 1]);
                float2 s2 = unpack2(acc[i * 4 + 2]);
                float2 s3 = unpack2(acc[i * 4 + 3]);
                float4 v = make_float4(s0.x + s0.y, s1.x + s1.y,
                                       s2.x + s2.y, s3.x + s3.y);
                *(float4*)(g_G1 + (size_t)(b0 + ty * 8 + i) * NG + rr0 + tx * 4) = v;
            }
        } else {
            ull acc[8];
            #pragma unroll
            for (int i = 0; i < 8; i++) acc[i] = 0ull;
            #pragma unroll
            for (int s = 0; s < 16; s++)
                slab24(Ap + s * 4096, Bp + s * 8192, aoff, boff, acc);
            #pragma unroll
            for (int i = 0; i < 2; i++) {
                float2 s0 = unpack2(acc[i * 4 + 0]);
                float2 s1 = unpack2(acc[i * 4 + 1]);
                float2 s2 = unpack2(acc[i * 4 + 2]);
                float2 s3 = unpack2(acc[i * 4 + 3]);
                float4 v = make_float4(s0.x + s0.y, s1.x + s1.y,
                                       s2.x + s2.y, s3.x + s3.y);
                *(float4*)(g_G2 + (size_t)(r0 + ty * 2 + i) * NG + rr0 + tx * 4) = v;
            }
        }
        grid_barrier();

        // fused LSTM: gates = pre + G1[b] + G2[b&255]
        {
            const float4* V1 = (const float4*)(g_G1 + (size_t)b_l * NG + 16 * uq);
            const float4* V2 = (const float4*)(g_G2 + (size_t)(b_l & 255) * NG + 16 * uq);
            float hv[4];
            #pragma unroll
            for (int w = 0; w < 4; w++) {
                float4 a = V1[w], b = V2[w];
                float gi = pr[4 * w + 0] + a.x + b.x;
                float gf = pr[4 * w + 1] + a.y + b.y;
                float gg = pr[4 * w + 2] + a.z + b.z;
                float go = pr[4 * w + 3] + a.w + b.w;
                float cv = sig_fast(gf) * creg[w] + sig_fast(gi) * tanh_fast(gg);
                creg[w] = cv;
                hv[w] = sig_fast(go) * tanh_fast(cv);
                hsum4[w] += hv[w];
            }
            *(float4*)(&g_h[(t + 1) & 1][b_l * NH + 4 * uq]) =
                make_float4(hv[0], hv[1], hv[2], hv[3]);
        }
        if (t + 1 < NT) grid_barrier();
    }

    *(float4*)(&g_hsum[b_l * NH + 4 * uq]) =
        make_float4(hsum4[0], hsum4[1], hsum4[2], hsum4[3]);
}

// ---------------- final ----------------
__global__ void final_kernel(float* __restrict__ out, const float* __restrict__ fc_b) {
    int b = blockIdx.x * blockDim.x + threadIdx.x;
    if (b >= NB) return;
    #pragma unroll
    for (int o = 0; o < 2; o++) {
        const float* f = g_fA + o * NK;
        const float* hsp = g_hsum + b * NH;
        float s = 0.f;
        for (int k = 0; k < NH; k++) s += f[k] * hsp[k];
        #pragma unroll
        for (int q = 0; q < 4; q++) {
            const float* hq = g_hsum + ((4 * b + q) & 1023) * NH;
            const float* fq = f + 128 + q * 128;
            for (int m = 0; m < NH; m++) s += fq[m] * hq[m];
        }
        out[b * 2 + o] = fc_b[o] + s * (1.f / (float)NT);
    }
}

// ---------------- launch ----------------
extern "C" void kernel_launch(void* const* d_in, const int* in_sizes, int n_in,
                              void* d_out, int out_size) {
    const float* x      = (const float*)d_in[0];
    const float* memory = (const float*)d_in[1];
    const float* rv0    = (const float*)d_in[2];
    const float* W_ih   = (const float*)d_in[3];
    const float* W_hh   = (const float*)d_in[4];
    const float* b_ih   = (const float*)d_in[5];
    const float* b_hh   = (const float*)d_in[6];
    const float* fc_w   = (const float*)d_in[7];
    const float* fc_b   = (const float*)d_in[8];
    float* out = (float*)d_out;

    static bool attr_done = false;
    if (!attr_done) {
        cudaFuncSetAttribute(pre_kernel, cudaFuncAttributeMaxDynamicSharedMemorySize, 73728);
        cudaFuncSetAttribute(recur_kernel, cudaFuncAttributeMaxDynamicSharedMemorySize, 197632);
        attr_done = true;
    }

    setup_kernel<<<1, 128>>>(memory, b_ih, b_hh, rv0, W_ih);
    buildA_kernel<<<dim3(514, 5), 128>>>(W_ih, W_hh, fc_w);
    buildX_kernel<<<dim3(512, 2), 128>>>(W_ih);
    pre_kernel<<<dim3(NT * NB / 128, NG / 64), 256, 73728>>>(x);
    recur_kernel<<<NCTA, 256, 197632>>>();
    final_kernel<<<4, 256>>>(out, fc_b);
}

// round 11
// speedup vs baseline: 1.5053x; 1.1408x over previous
#include <cuda_runtime.h>
#include <cstdint>

// ---------------- problem constants ----------------
#define NB 1024
#define NT 128
#define ND 256
#define NH 128
#define NG 512
#define NK 640
#define NCTA 128

typedef unsigned long long ull;
typedef ulonglong2 ull2;

// ---------------- f32x2 packed math ----------------
__device__ __forceinline__ ull ffma2(ull a, ull b, ull c) {
    ull d;
    asm("fma.rn.f32x2 %0, %1, %2, %3;" : "=l"(d) : "l"(a), "l"(b), "l"(c));
    return d;
}
__device__ __forceinline__ float2 unpack2(ull v) {
    float2 r; asm("mov.b64 {%0, %1}, %2;" : "=f"(r.x), "=f"(r.y) : "l"(v)); return r;
}
__device__ __forceinline__ float sig_fast(float x) { return 1.0f / (1.0f + __expf(-x)); }
__device__ __forceinline__ float tanh_fast(float x) { return 2.0f / (1.0f + __expf(-2.0f * x)) - 1.0f; }

__device__ __forceinline__ unsigned smem_u32(const void* p) {
    unsigned r;
    asm("{ .reg .u64 t; cvta.to.shared.u64 t, %1; cvt.u32.u64 %0, t; }" : "=r"(r) : "l"(p));
    return r;
}
#define CP16(dst, src) asm volatile("cp.async.cg.shared.global [%0], [%1], 16;" :: "r"(dst), "l"(src))
#define CP_COMMIT()    asm volatile("cp.async.commit_group;")
#define CP_WAIT1()     asm volatile("cp.async.wait_group 1;")
#define CP_WAIT0()     asm volatile("cp.async.wait_group 0;")

// ---------------- device scratch ----------------
__device__ float g_pre[(size_t)NT * NB * NG];   // [t*NB+b][rr] gate-reordered
__device__ float g_Wro[NG * NK];                // row rr=4u+gate, cols [W_hh | A_0..A_3]
__device__ float g_Wxro[NG * ND];
__device__ float g_memsm[NH * NH];
__device__ float g_fA[2 * NK];
__device__ float g_h[2][NB * NH];
__device__ float g_G1[(size_t)NB * NG];         // h @ W_hh^T   [1024][512]
__device__ float g_G2[256 * NG];                // Hg @ Wcat^T  [256][512]
__device__ float g_hsum[NB * NH];
__device__ float g_biasro[NG];
__device__ float g_c0ro[NG];

// barrier state: arrive and gen on SEPARATE 256B-aligned lines (kill false sharing)
struct __align__(256) BarState {
    unsigned arrive;
    unsigned pad[63];
    unsigned gen;       // offset 256
    unsigned pad2[63];
};
__device__ BarState g_bar;

// ---------------- grid barrier (sense-reversing, split lines) ----------------
__device__ __forceinline__ void grid_barrier() {
    __syncthreads();
    if (threadIdx.x == 0) {
        __threadfence();
        unsigned gen = *(volatile unsigned*)&g_bar.gen;   // read BEFORE arriving
        unsigned t = atomicAdd(&g_bar.arrive, 1u);
        if (t == (unsigned)(gridDim.x - 1)) {
            g_bar.arrive = 0;
            __threadfence();
            *(volatile unsigned*)&g_bar.gen = gen + 1;
        } else {
            while (*(volatile unsigned*)&g_bar.gen == gen) { __nanosleep(32); }
        }
        __threadfence();
    }
    __syncthreads();
}

// ---------------- 8x4 f32x2 tile over one 32-k slab (A linear, B swizzled) ----
__device__ __forceinline__ void slab84(const char* Ab, const char* Bb,
                                       const int aoff[8], const int boff[4],
                                       ull* acc /*32*/) {
    #pragma unroll
    for (int q = 0; q < 8; q++) {
        ull2 b[4];
        #pragma unroll
        for (int j = 0; j < 4; j++)
            b[j] = *(const ull2*)(Bb + (boff[j] ^ (q << 4)));
        #pragma unroll
        for (int i = 0; i < 8; i++) {
            ull2 a = *(const ull2*)(Ab + aoff[i] + (q << 4));
            #pragma unroll
            for (int j = 0; j < 4; j++) {
                acc[i * 4 + j] = ffma2(a.x, b[j].x, acc[i * 4 + j]);
                acc[i * 4 + j] = ffma2(a.y, b[j].y, acc[i * 4 + j]);
            }
        }
    }
}

// ---------------- 2x4 f32x2 tile over one 32-k slab ----------------
__device__ __forceinline__ void slab24(const char* Ab, const char* Bb,
                                       const int aoff[8], const int boff[4],
                                       ull* acc /*8*/) {
    #pragma unroll
    for (int q = 0; q < 8; q++) {
        ull2 b[4];
        #pragma unroll
        for (int j = 0; j < 4; j++)
            b[j] = *(const ull2*)(Bb + (boff[j] ^ (q << 4)));
        #pragma unroll
        for (int i = 0; i < 2; i++) {
            ull2 a = *(const ull2*)(Ab + aoff[i] + (q << 4));
            #pragma unroll
            for (int j = 0; j < 4; j++) {
                acc[i * 4 + j] = ffma2(a.x, b[j].x, acc[i * 4 + j]);
                acc[i * 4 + j] = ffma2(a.y, b[j].y, acc[i * 4 + j]);
            }
        }
    }
}

// ---------------- setup ----------------
__global__ void setup_kernel(const float* __restrict__ memory,
                             const float* __restrict__ b_ih,
                             const float* __restrict__ b_hh,
                             const float* __restrict__ rv0,
                             const float* __restrict__ W_ih) {
    int tid = threadIdx.x;
    float mx = -1e30f;
    for (int m = 0; m < NH; m++) mx = fmaxf(mx, memory[m * NH + tid]);
    float s = 0.f;
    for (int m = 0; m < NH; m++) s += expf(memory[m * NH + tid] - mx);
    float inv = 1.f / s;
    for (int m = 0; m < NH; m++)
        g_memsm[m * NH + tid] = expf(memory[m * NH + tid] - mx) * inv;

    for (int g = tid; g < NG; g += 128) {
        int u = g & 127, gate = g >> 7;
        int rr = 4 * u + gate;
        g_biasro[rr] = b_ih[g] + b_hh[g];
        float c0 = 0.f;
        const float* w = W_ih + (size_t)g * 768 + 256;
        for (int k = 0; k < 512; k++) c0 += rv0[k] * w[k];
        g_c0ro[rr] = c0;
    }
}

// ---------------- fold mem_sm into weights + reorder Wx (merged) ----------------
__global__ void buildA_kernel(const float* __restrict__ W_ih,
                              const float* __restrict__ W_hh,
                              const float* __restrict__ fc_w) {
    int row = blockIdx.x, q = blockIdx.y, j = threadIdx.x;
    if (q >= 5) {                       // Wx reorder part (q = 5,6)
        if (row < NG) {
            int u = row >> 2, gate = row & 3;
            int go = gate * 128 + u;
            g_Wxro[(size_t)row * ND + (q - 5) * 128 + j] =
                W_ih[(size_t)go * 768 + (q - 5) * 128 + j];
        }
        return;
    }
    if (row < NG) {
        int u = row >> 2, gate = row & 3;
        int go = gate * 128 + u;
        if (q == 0) {
            g_Wro[(size_t)row * NK + j] = W_hh[(size_t)go * NH + j];
        } else {
            const float* w = W_ih + (size_t)go * 768 + 256 + (q - 1) * 128;
            float s = 0.f;
            for (int m = 0; m < NH; m++) s += w[m] * g_memsm[m * NH + j];
            g_Wro[(size_t)row * NK + q * 128 + j] = s;
        }
    } else {
        int o = row - NG;
        if (q == 0) {
            g_fA[o * NK + j] = fc_w[o * NK + j];
        } else {
            const float* w = fc_w + o * NK + 128 + (q - 1) * 128;
            float s = 0.f;
            for (int m = 0; m < NH; m++) s += w[m] * g_memsm[m * NH + j];
            g_fA[o * NK + q * 128 + j] = s;
        }
    }
}

// ---------------- pre: [NT*NB,256] x [256,512] -> g_pre ----------------
__global__ __launch_bounds__(256, 2)
void pre_kernel(const float* __restrict__ x) {
    extern __shared__ char smc[];
    int r0  = blockIdx.x * 128;
    int rr0 = blockIdx.y * 64;
    int tid = threadIdx.x;
    int tx = tid & 15, ty = tid >> 4;

    int arow = tid >> 1;
    int aq0 = (tid & 1) * 4;
    int bcol = tid >> 2;
    int bq0 = (tid & 3) * 2;
    int bperm = (bcol ^ (bcol >> 3)) & 7;

    int rA = r0 + arow;
    int bb = rA & 1023, tA = rA >> 10;
    const float* xrow = x + ((size_t)bb * NT + tA) * ND;
    const float* wrow = g_Wxro + (size_t)(rr0 + bcol) * ND;
    unsigned smem_base = smem_u32(smc);

    #define PRE_ISSUE(s)                                                        \
    {                                                                           \
        unsigned stg = smem_base + ((s) % 3) * 24576u;                          \
        unsigned ab  = stg + (unsigned)(arow * 128);                            \
        unsigned bbs = stg + 16384u + (unsigned)(bcol * 128);                   \
        const float* ap = xrow + (s) * 32;                                      \
        const float* bp = wrow + (s) * 32;                                      \
        _Pragma("unroll")                                                       \
        for (int p = 0; p < 4; p++) { int qn = aq0 + p; CP16(ab + qn * 16, ap + qn * 4); } \
        _Pragma("unroll")                                                       \
        for (int p = 0; p < 2; p++) { int qn = bq0 + p; CP16(bbs + ((qn ^ bperm) << 4), bp + qn * 4); } \
        CP_COMMIT();                                                            \
    }

    int aoff[8], boff[4];
    #pragma unroll
    for (int i = 0; i < 8; i++)
        aoff[i] = (ty * 8 + i) * 128;
    #pragma unroll
    for (int j = 0; j < 4; j++) {
        int cc = tx * 4 + j;
        boff[j] = (cc * 128) ^ ((((cc ^ (cc >> 3)) & 7)) << 4);
    }

    ull acc[32];
    #pragma unroll
    for (int i = 0; i < 32; i++) acc[i] = 0ull;

    const int NS = ND / 32;
    PRE_ISSUE(0);
    PRE_ISSUE(1);
    for (int s = 0; s < NS; s++) {
        if (s + 2 < NS) { CP_WAIT1(); } else { CP_WAIT0(); }
        __syncthreads();
        if (s + 2 < NS) PRE_ISSUE(s + 2);
        const char* Ab = smc + (s % 3) * 24576;
        slab84(Ab, Ab + 16384, aoff, boff, acc);
    }
    #undef PRE_ISSUE

    int tt = r0 >> 10;
    #pragma unroll
    for (int i = 0; i < 8; i++) {
        int r = r0 + ty * 8 + i;
        int rr = rr0 + tx * 4;
        float2 s0 = unpack2(acc[i * 4 + 0]);
        float2 s1 = unpack2(acc[i * 4 + 1]);
        float2 s2 = unpack2(acc[i * 4 + 2]);
        float2 s3 = unpack2(acc[i * 4 + 3]);
        float4 v;
        v.x = s0.x + s0.y + g_biasro[rr];
        v.y = s1.x + s1.y + g_biasro[rr + 1];
        v.z = s2.x + s2.y + g_biasro[rr + 2];
        v.w = s3.x + s3.y + g_biasro[rr + 3];
        if (tt == 0) {
            v.x += g_c0ro[rr];     v.y += g_c0ro[rr + 1];
            v.z += g_c0ro[rr + 2]; v.w += g_c0ro[rr + 3];
        }
        *(float4*)(g_pre + (size_t)r * NG + rr) = v;
    }
}

// ---------------- persistent recurrence ----------------
// 128 CTAs. cta<64: G1 job (128 batches x 64 cols, K=128).
//           cta>=64: G2 job (32 Hg-rows x 64 cols, K=512).
// smem (1KB-aligned): B @0 | A @131072 (64KB)
__global__ __launch_bounds__(256)
void recur_kernel() {
    extern __shared__ char dsm[];
    unsigned raw = smem_u32(dsm);
    unsigned db = (raw + 1023u) & ~1023u;
    char* smb = dsm + (db - raw);
    unsigned Bsm = db;
    unsigned Asm = db + 131072u;
    char* Bp = smb;
    char* Ap = smb + 131072;

    int tid = threadIdx.x;
    int cta = blockIdx.x;
    bool isG1 = cta < 64;
    int jt = isG1 ? cta : cta - 64;
    int rr0 = (jt >> 3) * 64;
    int b0 = (jt & 7) * 128;       // G1 batch tile
    int r0 = (jt & 7) * 32;        // G2 Hg-row tile
    int tx = tid & 15, ty = tid >> 4;

    // LSTM cell ownership: 4 units of one batch
    int T = cta * 256 + tid;
    int b_l = T >> 5;
    int uq = T & 31;

    *(float4*)(&g_h[0][b_l * NH + 4 * uq]) = make_float4(0.f, 0.f, 0.f, 0.f);

    // resident B fill (swizzled)
    {
        int nsl = isG1 ? 4 : 16;
        int koff = isG1 ? 0 : 128;
        for (int ci = tid; ci < nsl * 512; ci += 256) {
            int s = ci >> 9;
            int rem = ci & 511;
            int c = rem >> 3, qn = rem & 7;
            int perm = (c ^ (c >> 3)) & 7;
            CP16(Bsm + (unsigned)(s * 8192 + c * 128 + ((qn ^ perm) << 4)),
                 g_Wro + (size_t)(rr0 + c) * NK + koff + s * 32 + qn * 4);
        }
        CP_COMMIT(); CP_WAIT0();
    }
    grid_barrier();

    int aoff[8], boff[4];
    if (isG1) {
        #pragma unroll
        for (int i = 0; i < 8; i++)
            aoff[i] = (ty * 8 + i) * 128;
    } else {
        #pragma unroll
        for (int i = 0; i < 2; i++)
            aoff[i] = (ty * 2 + i) * 128;
    }
    #pragma unroll
    for (int j = 0; j < 4; j++) {
        int cc = tx * 4 + j;
        boff[j] = (cc * 128) ^ ((((cc ^ (cc >> 3)) & 7)) << 4);
    }

    float creg[4] = {0.f, 0.f, 0.f, 0.f};
    float hsum4[4] = {0.f, 0.f, 0.f, 0.f};

    for (int t = 0; t < NT; t++) {
        const float* hb = g_h[t & 1];

        // A fill: 64KB in one burst, unswizzled rows
        if (isG1) {
            #pragma unroll
            for (int i = 0; i < 16; i++) {
                int ci = i * 256 + tid;
                int s = ci >> 10, rem = ci & 1023, r = rem >> 3, qn = rem & 7;
                CP16(Asm + (unsigned)(s * 16384 + r * 128 + qn * 16),
                     hb + (size_t)(b0 + r) * NH + s * 32 + qn * 4);
            }
        } else {
            #pragma unroll
            for (int i = 0; i < 16; i++) {
                int ci = i * 256 + tid;
                int s = ci >> 8, rem = ci & 255, r = rem >> 3, qn = rem & 7;
                CP16(Asm + (unsigned)(s * 4096 + r * 128 + qn * 16),
                     hb + (size_t)r0 * 512 + r * 512 + s * 32 + qn * 4);
            }
        }
        CP_COMMIT();

        // prefetch pre for my LSTM cells (independent of cp.async)
        float pr[16];
        {
            const float4* PR = (const float4*)(g_pre + ((size_t)t * NB + b_l) * NG + 16 * uq);
            #pragma unroll
            for (int w = 0; w < 4; w++) *(float4*)(pr + 4 * w) = PR[w];
        }

        CP_WAIT0();
        __syncthreads();

        if (isG1) {
            ull acc[32];
            #pragma unroll
            for (int i = 0; i < 32; i++) acc[i] = 0ull;
            #pragma unroll
            for (int s = 0; s < 4; s++)
                slab84(Ap + s * 16384, Bp + s * 8192, aoff, boff, acc);
            #pragma unroll
            for (int i = 0; i < 8; i++) {
                float2 s0 = unpack2(acc[i * 4 + 0]);
                float2 s1 = unpack2(acc[i * 4 + 1]);
                float2 s2 = unpack2(acc[i * 4 + 2]);
                float2 s3 = unpack2(acc[i * 4 + 3]);
                float4 v = make_float4(s0.x + s0.y, s1.x + s1.y,
                                       s2.x + s2.y, s3.x + s3.y);
                *(float4*)(g_G1 + (size_t)(b0 + ty * 8 + i) * NG + rr0 + tx * 4) = v;
            }
        } else {
            ull acc[8];
            #pragma unroll
            for (int i = 0; i < 8; i++) acc[i] = 0ull;
            #pragma unroll
            for (int s = 0; s < 16; s++)
                slab24(Ap + s * 4096, Bp + s * 8192, aoff, boff, acc);
            #pragma unroll
            for (int i = 0; i < 2; i++) {
                float2 s0 = unpack2(acc[i * 4 + 0]);
                float2 s1 = unpack2(acc[i * 4 + 1]);
                float2 s2 = unpack2(acc[i * 4 + 2]);
                float2 s3 = unpack2(acc[i * 4 + 3]);
                float4 v = make_float4(s0.x + s0.y, s1.x + s1.y,
                                       s2.x + s2.y, s3.x + s3.y);
                *(float4*)(g_G2 + (size_t)(r0 + ty * 2 + i) * NG + rr0 + tx * 4) = v;
            }
        }
        grid_barrier();

        // fused LSTM: gates = pre + G1[b] + G2[b&255]
        {
            const float4* V1 = (const float4*)(g_G1 + (size_t)b_l * NG + 16 * uq);
            const float4* V2 = (const float4*)(g_G2 + (size_t)(b_l & 255) * NG + 16 * uq);
            float hv[4];
            #pragma unroll
            for (int w = 0; w < 4; w++) {
                float4 a = V1[w], b = V2[w];
                float gi = pr[4 * w + 0] + a.x + b.x;
                float gf = pr[4 * w + 1] + a.y + b.y;
                float gg = pr[4 * w + 2] + a.z + b.z;
                float go = pr[4 * w + 3] + a.w + b.w;
                float cv = sig_fast(gf) * creg[w] + sig_fast(gi) * tanh_fast(gg);
                creg[w] = cv;
                hv[w] = sig_fast(go) * tanh_fast(cv);
                hsum4[w] += hv[w];
            }
            *(float4*)(&g_h[(t + 1) & 1][b_l * NH + 4 * uq]) =
                make_float4(hv[0], hv[1], hv[2], hv[3]);
        }
        if (t + 1 < NT) grid_barrier();
    }

    *(float4*)(&g_hsum[b_l * NH + 4 * uq]) =
        make_float4(hsum4[0], hsum4[1], hsum4[2], hsum4[3]);
}

// ---------------- final ----------------
__global__ void final_kernel(float* __restrict__ out, const float* __restrict__ fc_b) {
    int b = blockIdx.x * blockDim.x + threadIdx.x;
    if (b >= NB) return;
    #pragma unroll
    for (int o = 0; o < 2; o++) {
        const float* f = g_fA + o * NK;
        const float* hsp = g_hsum + b * NH;
        float s = 0.f;
        for (int k = 0; k < NH; k++) s += f[k] * hsp[k];
        #pragma unroll
        for (int q = 0; q < 4; q++) {
            const float* hq = g_hsum + ((4 * b + q) & 1023) * NH;
            const float* fq = f + 128 + q * 128;
            for (int m = 0; m < NH; m++) s += fq[m] * hq[m];
        }
        out[b * 2 + o] = fc_b[o] + s * (1.f / (float)NT);
    }
}

// ---------------- launch ----------------
extern "C" void kernel_launch(void* const* d_in, const int* in_sizes, int n_in,
                              void* d_out, int out_size) {
    const float* x      = (const float*)d_in[0];
    const float* memory = (const float*)d_in[1];
    const float* rv0    = (const float*)d_in[2];
    const float* W_ih   = (const float*)d_in[3];
    const float* W_hh   = (const float*)d_in[4];
    const float* b_ih   = (const float*)d_in[5];
    const float* b_hh   = (const float*)d_in[6];
    const float* fc_w   = (const float*)d_in[7];
    const float* fc_b   = (const float*)d_in[8];
    float* out = (float*)d_out;

    static bool attr_done = false;
    if (!attr_done) {
        cudaFuncSetAttribute(pre_kernel, cudaFuncAttributeMaxDynamicSharedMemorySize, 73728);
        cudaFuncSetAttribute(recur_kernel, cudaFuncAttributeMaxDynamicSharedMemorySize, 197632);
        attr_done = true;
    }

    setup_kernel<<<1, 128>>>(memory, b_ih, b_hh, rv0, W_ih);
    buildA_kernel<<<dim3(514, 7), 128>>>(W_ih, W_hh, fc_w);
    pre_kernel<<<dim3(NT * NB / 128, NG / 64), 256, 73728>>>(x);
    recur_kernel<<<NCTA, 256, 197632>>>();
    final_kernel<<<4, 256>>>(out, fc_b);
}